// round 11
// baseline (speedup 1.0000x reference)
#include <cuda_runtime.h>
#include <cuda_fp16.h>
#include <cstdint>

#define NN 512
#define GRID 148
#define TPB 512
#define NT 2048   // 4 b x 4 jt x 128 i-quads

// ---- SMEM byte offsets ----
#define OB_W1T 0        // fp16 [n=128][k=64]  stride 72 fp16 (144B)  -> 18432
#define OB_W2T 18432    // fp16 [n=128][h=128] stride 136 fp16 (272B) -> 34816
#define OB_DH  53248    // fp16 diff [j=128][72] stride 144B, x4 groups -> 73728
#define OB_YS  126976   // f32 [128][68] -> 34816
#define OB_TV2 161792   // half2 tv [4][64] u32 -> 1024
#define OB_B2S 162816   // f32 [128]
#define OB_W3S 163328   // f32 [128]
#define SMEM_BYTES 163840

__device__ __forceinline__ uint32_t smem_u32(const void* p) {
    uint32_t a;
    asm("{ .reg .u64 t; cvta.to.shared.u64 t, %1; cvt.u32.u64 %0, t; }" : "=r"(a) : "l"(p));
    return a;
}
__device__ __forceinline__ uint32_t pack2(float e0, float e1) {
    __half2 h = __floats2half2_rn(e0, e1);
    return *(uint32_t*)&h;
}
__device__ __forceinline__ uint32_t relu_add2(uint32_t v, uint32_t tv) {
    __half2 a = __hadd2(*(__half2*)&v, *(__half2*)&tv);
    __half2 z = __float2half2_rn(0.f);
    __half2 m = __hmax2(a, z);
    return *(uint32_t*)&m;
}
// Volatile ldmatrix: for A fragments (reads data this warp just stored).
__device__ __forceinline__ void ldsm_x4_v(uint32_t& r0, uint32_t& r1, uint32_t& r2, uint32_t& r3,
                                          uint32_t addr) {
    asm volatile("ldmatrix.sync.aligned.m8n8.x4.shared.b16 {%0,%1,%2,%3}, [%4];"
                 : "=r"(r0), "=r"(r1), "=r"(r2), "=r"(r3) : "r"(addr));
}
// Non-volatile ldmatrix: for B fragments (immutable weights) -- lets ptxas
// software-pipeline loads ahead of consuming MMAs (CUTLASS-style).
__device__ __forceinline__ void ldsm_x4(uint32_t& r0, uint32_t& r1, uint32_t& r2, uint32_t& r3,
                                        uint32_t addr) {
    asm("ldmatrix.sync.aligned.m8n8.x4.shared.b16 {%0,%1,%2,%3}, [%4];"
        : "=r"(r0), "=r"(r1), "=r"(r2), "=r"(r3) : "r"(addr));
}
// Non-volatile MMA: pure register computation, free to be scheduled.
__device__ __forceinline__ void mma_f16(float* c, const uint32_t* a,
                                        uint32_t b0, uint32_t b1) {
    asm("mma.sync.aligned.m16n8k16.row.col.f32.f16.f16.f32 "
        "{%0,%1,%2,%3},{%4,%5,%6,%7},{%8,%9},{%0,%1,%2,%3};"
        : "+f"(c[0]), "+f"(c[1]), "+f"(c[2]), "+f"(c[3])
        : "r"(a[0]), "r"(a[1]), "r"(a[2]), "r"(a[3]), "r"(b0), "r"(b1));
}

__global__ void __launch_bounds__(TPB, 1)
pairmlp_f16(const float* __restrict__ x, const float* __restrict__ y,
            const float* __restrict__ t, const float* __restrict__ W1,
            const float* __restrict__ b1, const float* __restrict__ W2,
            const float* __restrict__ b2, const float* __restrict__ W3,
            const float* __restrict__ b3, float* __restrict__ out)
{
    extern __shared__ char sm[];
    float* ys  = (float*)(sm + OB_YS);
    uint32_t* tv2 = (uint32_t*)(sm + OB_TV2);
    float* b2s = (float*)(sm + OB_B2S);
    float* w3s = (float*)(sm + OB_W3S);
    __half* w1t = (__half*)(sm + OB_W1T);
    __half* w2t = (__half*)(sm + OB_W2T);

    const int tid = threadIdx.x;
    const int wid = tid >> 5;
    const int l   = tid & 31;
    const int grp = wid >> 2;          // 0..3: which i of the quad
    const int m32 = (wid & 3) * 32;    // warp's 32 j-rows
    const uint32_t sb = smem_u32(sm);
    const uint32_t dhb = sb + OB_DH + (uint32_t)grp * 18432u;

    // ---- one-time staging ----
    for (int idx = tid; idx < 64 * 128; idx += TPB) {
        int k = idx >> 7, n = idx & 127;
        w1t[n * 72 + k] = __float2half(W1[k * 128 + n]);
    }
    for (int idx = tid; idx < 128 * 128; idx += TPB) {
        int h = idx >> 7, n = idx & 127;
        w2t[n * 136 + h] = __float2half(W2[h * 128 + n]);
    }
    for (int idx = tid; idx < 4 * 64; idx += TPB) {
        int bb = idx >> 6, hp = idx & 63;
        float s0 = b1[2 * hp], s1 = b1[2 * hp + 1];
        #pragma unroll
        for (int d = 0; d < 32; d++) {
            float tv = t[bb * 32 + d];
            s0 += tv * W1[(64 + d) * 128 + 2 * hp];
            s1 += tv * W1[(64 + d) * 128 + 2 * hp + 1];
        }
        tv2[bb * 64 + hp] = pack2(s0, s1);
    }
    if (tid < 128) { b2s[tid] = b2[tid]; w3s[tid] = W3[tid]; }
    const float b3v = b3[0];
    __syncthreads();

    // ---- per-lane ldmatrix addresses ----
    const int g2 = l >> 3, r = l & 7;
    const uint32_t aA  = dhb + (uint32_t)(m32 + (g2 & 1) * 8 + r) * 144 + (uint32_t)(g2 >> 1) * 16;
    const uint32_t bB1 = sb + OB_W1T + (uint32_t)((g2 >> 1) * 8 + r) * 144 + (uint32_t)(g2 & 1) * 16;
    const uint32_t bB2 = sb + OB_W2T + (uint32_t)((g2 >> 1) * 8 + r) * 272 + (uint32_t)(g2 & 1) * 16;

    const int qr = l >> 2, qc = l & 3;
    const int start = (NT * blockIdx.x) / GRID;
    const int end   = (NT * (blockIdx.x + 1)) / GRID;
    int cur_bjt = -1;

    for (int tau = start; tau < end; ++tau) {
        const int bjt = tau >> 7;          // 0..15
        const int q   = tau & 127;
        const int b   = bjt >> 2;
        const int jt  = bjt & 3;
        const int i   = q * 4 + grp;       // always < 512

        if (bjt != cur_bjt) {
            __syncthreads();
            const float4* yg = (const float4*)(y + ((size_t)(b * NN + jt * 128)) * 64);
            for (int idx = tid; idx < 128 * 16; idx += TPB) {
                int rr = idx >> 4, gg = idx & 15;
                float4 v = yg[rr * 16 + gg];
                float* dst = ys + rr * 68 + gg * 4;
                dst[0] = v.x; dst[1] = v.y; dst[2] = v.z; dst[3] = v.w;
            }
            cur_bjt = bjt;
            __syncthreads();
        }

        // ---- diff^2 -> DH strip (fp16), rows m32..m32+31, k-chunk qc*16 ----
        {
            const float4* xg = (const float4*)(x + ((size_t)(b * NN + i)) * 64 + qc * 16);
            float4 xv[4];
            #pragma unroll
            for (int qq = 0; qq < 4; qq++) xv[qq] = xg[qq];
            #pragma unroll
            for (int rr = 0; rr < 4; rr++) {
                int row = m32 + qr + rr * 8;
                const float4* yrow = (const float4*)(ys + row * 68 + qc * 16);
                uint32_t base = dhb - sb + (uint32_t)row * 144 + (uint32_t)qc * 32;
                uint32_t u[8];
                #pragma unroll
                for (int qq = 0; qq < 4; qq++) {
                    float4 yv = yrow[qq];
                    float d0 = xv[qq].x - yv.x, d1 = xv[qq].y - yv.y;
                    float d2 = xv[qq].z - yv.z, d3 = xv[qq].w - yv.w;
                    u[2 * qq]     = pack2(d0 * d0, d1 * d1);
                    u[2 * qq + 1] = pack2(d2 * d2, d3 * d3);
                }
                *(uint4*)(sm + base)      = make_uint4(u[0], u[1], u[2], u[3]);
                *(uint4*)(sm + base + 16) = make_uint4(u[4], u[5], u[6], u[7]);
            }
        }
        __syncwarp();

        // ---- preload GEMM1 A fragments (diff), 2 m-blocks x 4 k-steps ----
        uint32_t a1[2][4][4];
        #pragma unroll
        for (int mb = 0; mb < 2; mb++)
            #pragma unroll
            for (int ks = 0; ks < 4; ks++)
                ldsm_x4_v(a1[mb][ks][0], a1[mb][ks][1], a1[mb][ks][2], a1[mb][ks][3],
                          aA + (uint32_t)mb * (16 * 144) + (uint32_t)ks * 32);

        // ---- GEMM1 (M=32, K=64) in 4 n-quarters; epilogue1 -> af in regs ----
        uint32_t af[2][8][4];
        #pragma unroll
        for (int nq = 0; nq < 4; nq++) {
            float acc[2][4][4];
            #pragma unroll
            for (int mb = 0; mb < 2; mb++)
                #pragma unroll
                for (int nt = 0; nt < 4; nt++)
                    #pragma unroll
                    for (int c = 0; c < 4; c++) acc[mb][nt][c] = 0.f;

            const uint32_t bbase = bB1 + (uint32_t)nq * (32 * 144);
            #pragma unroll
            for (int ks = 0; ks < 4; ks++) {
                #pragma unroll
                for (int p = 0; p < 2; p++) {
                    uint32_t b0, b1v, b2v, b3r;
                    ldsm_x4(b0, b1v, b2v, b3r, bbase + (uint32_t)p * (16 * 144) + (uint32_t)ks * 32);
                    mma_f16(acc[0][2 * p],     a1[0][ks], b0, b1v);
                    mma_f16(acc[0][2 * p + 1], a1[0][ks], b2v, b3r);
                    mma_f16(acc[1][2 * p],     a1[1][ks], b0, b1v);
                    mma_f16(acc[1][2 * p + 1], a1[1][ks], b2v, b3r);
                }
            }
            // convert quarter to af k-blocks 2nq, 2nq+1
            const uint32_t* tvb = tv2 + b * 64;
            #pragma unroll
            for (int j = 0; j < 2; j++) {
                int ksg = 2 * nq + j;
                uint32_t tv0 = tvb[(4 * nq + 2 * j) * 4 + qc];
                uint32_t tv1 = tvb[(4 * nq + 2 * j + 1) * 4 + qc];
                #pragma unroll
                for (int mb = 0; mb < 2; mb++) {
                    af[mb][ksg][0] = relu_add2(pack2(acc[mb][2 * j][0],     acc[mb][2 * j][1]),     tv0);
                    af[mb][ksg][1] = relu_add2(pack2(acc[mb][2 * j][2],     acc[mb][2 * j][3]),     tv0);
                    af[mb][ksg][2] = relu_add2(pack2(acc[mb][2 * j + 1][0], acc[mb][2 * j + 1][1]), tv1);
                    af[mb][ksg][3] = relu_add2(pack2(acc[mb][2 * j + 1][2], acc[mb][2 * j + 1][3]), tv1);
                }
            }
        }

        // ---- GEMM2 (M=32, K=128) in 4 n-quarters; fused epilogue2 ----
        float part[4] = {0.f, 0.f, 0.f, 0.f};
        #pragma unroll
        for (int nq = 0; nq < 4; nq++) {
            float acc2[2][4][4];
            #pragma unroll
            for (int mb = 0; mb < 2; mb++)
                #pragma unroll
                for (int nt = 0; nt < 4; nt++)
                    #pragma unroll
                    for (int c = 0; c < 4; c++) acc2[mb][nt][c] = 0.f;

            const uint32_t bbase = bB2 + (uint32_t)nq * (32 * 272);
            #pragma unroll
            for (int ks = 0; ks < 8; ks++) {
                #pragma unroll
                for (int p = 0; p < 2; p++) {
                    uint32_t b0, b1v, b2v, b3r;
                    ldsm_x4(b0, b1v, b2v, b3r, bbase + (uint32_t)p * (16 * 272) + (uint32_t)ks * 32);
                    mma_f16(acc2[0][2 * p],     af[0][ks], b0, b1v);
                    mma_f16(acc2[0][2 * p + 1], af[0][ks], b2v, b3r);
                    mma_f16(acc2[1][2 * p],     af[1][ks], b0, b1v);
                    mma_f16(acc2[1][2 * p + 1], af[1][ks], b2v, b3r);
                }
            }
            const float* b2b = b2s + nq * 32;
            const float* w3b = w3s + nq * 32;
            #pragma unroll
            for (int nt = 0; nt < 4; nt++) {
                int h0 = nt * 8 + 2 * qc;
                float2 b2v = *(const float2*)(b2b + h0);
                float2 w3v = *(const float2*)(w3b + h0);
                #pragma unroll
                for (int mb = 0; mb < 2; mb++) {
                    part[mb * 2]     += fmaxf(acc2[mb][nt][0] + b2v.x, 0.f) * w3v.x
                                      + fmaxf(acc2[mb][nt][1] + b2v.y, 0.f) * w3v.y;
                    part[mb * 2 + 1] += fmaxf(acc2[mb][nt][2] + b2v.x, 0.f) * w3v.x
                                      + fmaxf(acc2[mb][nt][3] + b2v.y, 0.f) * w3v.y;
                }
            }
        }

        #pragma unroll
        for (int p = 0; p < 4; p++) {
            part[p] += __shfl_xor_sync(0xffffffff, part[p], 1);
            part[p] += __shfl_xor_sync(0xffffffff, part[p], 2);
        }
        if (qc == 0) {
            size_t obase = ((size_t)(b * NN + i)) * NN + jt * 128 + m32;
            out[obase + qr]      = part[0] + b3v;
            out[obase + 8 + qr]  = part[1] + b3v;
            out[obase + 16 + qr] = part[2] + b3v;
            out[obase + 24 + qr] = part[3] + b3v;
        }
    }
}

extern "C" void kernel_launch(void* const* d_in, const int* in_sizes, int n_in,
                              void* d_out, int out_size)
{
    const float* x  = (const float*)d_in[0];
    const float* y  = (const float*)d_in[1];
    const float* t  = (const float*)d_in[2];
    const float* W1 = (const float*)d_in[3];
    const float* b1 = (const float*)d_in[4];
    const float* W2 = (const float*)d_in[5];
    const float* b2 = (const float*)d_in[6];
    const float* W3 = (const float*)d_in[7];
    const float* b3 = (const float*)d_in[8];
    float* out = (float*)d_out;

    cudaFuncSetAttribute(pairmlp_f16,
                         cudaFuncAttributeMaxDynamicSharedMemorySize, SMEM_BYTES);
    pairmlp_f16<<<GRID, TPB, SMEM_BYTES>>>(x, y, t, W1, b1, W2, b2, W3, b3, out);
}

// round 12
// speedup vs baseline: 1.0958x; 1.0958x over previous
#include <cuda_runtime.h>
#include <cuda_fp16.h>
#include <cstdint>

#define NN 512
#define GRID 148
#define TPB 384
#define NT 2736   // 16 bjt x 171 i-triples

// ---- SMEM byte offsets ----
#define OB_W1T 0        // fp16 [n=128][k=64]  stride 72 fp16 (144B)  -> 18432
#define OB_W2T 18432    // fp16 [n=128][h=128] stride 136 fp16 (272B) -> 34816
#define OB_DH  53248    // fp16 diff [j=128][72] stride 144B, x3 groups -> 55296
#define OB_YS  108544   // f32 [128][68] -> 34816
#define OB_TV2 143360   // half2 tv [4][64] u32 -> 1024
#define OB_B2S 144384   // f32 [128]
#define OB_W3S 144896   // f32 [128]
#define SMEM_BYTES 145408

__device__ __forceinline__ uint32_t smem_u32(const void* p) {
    uint32_t a;
    asm("{ .reg .u64 t; cvta.to.shared.u64 t, %1; cvt.u32.u64 %0, t; }" : "=r"(a) : "l"(p));
    return a;
}
__device__ __forceinline__ uint32_t pack2(float e0, float e1) {
    __half2 h = __floats2half2_rn(e0, e1);
    return *(uint32_t*)&h;
}
__device__ __forceinline__ uint32_t relu_add2(uint32_t v, uint32_t tv) {
    __half2 a = __hadd2(*(__half2*)&v, *(__half2*)&tv);
    __half2 z = __float2half2_rn(0.f);
    __half2 m = __hmax2(a, z);
    return *(uint32_t*)&m;
}
__device__ __forceinline__ void ldsm_x4(uint32_t* r, uint32_t addr) {
    asm volatile("ldmatrix.sync.aligned.m8n8.x4.shared.b16 {%0,%1,%2,%3}, [%4];"
                 : "=r"(r[0]), "=r"(r[1]), "=r"(r[2]), "=r"(r[3]) : "r"(addr));
}
__device__ __forceinline__ void mma_f16(float* c, const uint32_t* a,
                                        uint32_t b0, uint32_t b1) {
    asm volatile("mma.sync.aligned.m16n8k16.row.col.f32.f16.f16.f32 "
                 "{%0,%1,%2,%3},{%4,%5,%6,%7},{%8,%9},{%0,%1,%2,%3};"
                 : "+f"(c[0]), "+f"(c[1]), "+f"(c[2]), "+f"(c[3])
                 : "r"(a[0]), "r"(a[1]), "r"(a[2]), "r"(a[3]), "r"(b0), "r"(b1));
}

__global__ void __launch_bounds__(TPB, 1)
pairmlp_f16(const float* __restrict__ x, const float* __restrict__ y,
            const float* __restrict__ t, const float* __restrict__ W1,
            const float* __restrict__ b1, const float* __restrict__ W2,
            const float* __restrict__ b2, const float* __restrict__ W3,
            const float* __restrict__ b3, float* __restrict__ out)
{
    extern __shared__ char sm[];
    float* ys  = (float*)(sm + OB_YS);
    uint32_t* tv2 = (uint32_t*)(sm + OB_TV2);
    float* b2s = (float*)(sm + OB_B2S);
    float* w3s = (float*)(sm + OB_W3S);
    __half* w1t = (__half*)(sm + OB_W1T);
    __half* w2t = (__half*)(sm + OB_W2T);

    const int tid = threadIdx.x;
    const int wid = tid >> 5;
    const int l   = tid & 31;
    const int grp = wid >> 2;          // 0..2: which i of the triple
    const int m32 = (wid & 3) * 32;    // warp's 32 j-rows
    const uint32_t sb = smem_u32(sm);
    const uint32_t dhb = sb + OB_DH + (uint32_t)grp * 18432u;

    // ---- one-time staging ----
    for (int idx = tid; idx < 64 * 128; idx += TPB) {
        int k = idx >> 7, n = idx & 127;
        w1t[n * 72 + k] = __float2half(W1[k * 128 + n]);
    }
    for (int idx = tid; idx < 128 * 128; idx += TPB) {
        int h = idx >> 7, n = idx & 127;
        w2t[n * 136 + h] = __float2half(W2[h * 128 + n]);
    }
    for (int idx = tid; idx < 4 * 64; idx += TPB) {
        int bb = idx >> 6, hp = idx & 63;
        float s0 = b1[2 * hp], s1 = b1[2 * hp + 1];
        #pragma unroll
        for (int d = 0; d < 32; d++) {
            float tv = t[bb * 32 + d];
            s0 += tv * W1[(64 + d) * 128 + 2 * hp];
            s1 += tv * W1[(64 + d) * 128 + 2 * hp + 1];
        }
        tv2[bb * 64 + hp] = pack2(s0, s1);
    }
    if (tid < 128) { b2s[tid] = b2[tid]; w3s[tid] = W3[tid]; }
    const float b3v = b3[0];
    __syncthreads();

    // ---- per-lane ldmatrix addresses ----
    const int g2 = l >> 3, r = l & 7;
    const uint32_t aA  = dhb + (uint32_t)(m32 + (g2 & 1) * 8 + r) * 144 + (uint32_t)(g2 >> 1) * 16;
    const uint32_t bB1 = sb + OB_W1T + (uint32_t)((g2 >> 1) * 8 + r) * 144 + (uint32_t)(g2 & 1) * 16;
    const uint32_t bB2 = sb + OB_W2T + (uint32_t)((g2 >> 1) * 8 + r) * 272 + (uint32_t)(g2 & 1) * 16;

    const int qr = l >> 2, qc = l & 3;
    const int start = (NT * blockIdx.x) / GRID;
    const int end   = (NT * (blockIdx.x + 1)) / GRID;
    int cur_bjt = -1;

    for (int tau = start; tau < end; ++tau) {
        const int bjt = tau / 171;
        const int q   = tau - bjt * 171;
        const int b   = bjt >> 2;
        const int jt  = bjt & 3;
        const int i   = q * 3 + grp;
        const int ild = (i < NN) ? i : (NN - 1);

        if (bjt != cur_bjt) {
            __syncthreads();
            const float4* yg = (const float4*)(y + ((size_t)(b * NN + jt * 128)) * 64);
            for (int idx = tid; idx < 128 * 16; idx += TPB) {
                int rr = idx >> 4, gg = idx & 15;
                float4 v = yg[rr * 16 + gg];
                float* dst = ys + rr * 68 + gg * 4;
                dst[0] = v.x; dst[1] = v.y; dst[2] = v.z; dst[3] = v.w;
            }
            cur_bjt = bjt;
            __syncthreads();
        }

        // ---- diff^2 -> DH strip (fp16), rows m32..m32+31, k-chunk qc*16 ----
        {
            const float4* xg = (const float4*)(x + ((size_t)(b * NN + ild)) * 64 + qc * 16);
            float4 xv[4];
            #pragma unroll
            for (int qq = 0; qq < 4; qq++) xv[qq] = xg[qq];
            #pragma unroll
            for (int rr = 0; rr < 4; rr++) {
                int row = m32 + qr + rr * 8;
                const float4* yrow = (const float4*)(ys + row * 68 + qc * 16);
                uint32_t base = dhb - sb + (uint32_t)row * 144 + (uint32_t)qc * 32;
                uint32_t u[8];
                #pragma unroll
                for (int qq = 0; qq < 4; qq++) {
                    float4 yv = yrow[qq];
                    float d0 = xv[qq].x - yv.x, d1 = xv[qq].y - yv.y;
                    float d2 = xv[qq].z - yv.z, d3 = xv[qq].w - yv.w;
                    u[2 * qq]     = pack2(d0 * d0, d1 * d1);
                    u[2 * qq + 1] = pack2(d2 * d2, d3 * d3);
                }
                *(uint4*)(sm + base)      = make_uint4(u[0], u[1], u[2], u[3]);
                *(uint4*)(sm + base + 16) = make_uint4(u[4], u[5], u[6], u[7]);
            }
        }
        __syncwarp();

        // ---- preload GEMM1 A fragments (diff), 2 m-blocks x 4 k-steps ----
        uint32_t a1[2][4][4];
        #pragma unroll
        for (int mb = 0; mb < 2; mb++)
            #pragma unroll
            for (int ks = 0; ks < 4; ks++)
                ldsm_x4(a1[mb][ks], aA + (uint32_t)mb * (16 * 144) + (uint32_t)ks * 32);

        // ---- GEMM1 (M=32, K=64) in 4 n-quarters, B double-buffered ----
        uint32_t af[2][8][4];
        #pragma unroll
        for (int nq = 0; nq < 4; nq++) {
            float acc[2][4][4];
            #pragma unroll
            for (int mb = 0; mb < 2; mb++)
                #pragma unroll
                for (int nt = 0; nt < 4; nt++)
                    #pragma unroll
                    for (int c = 0; c < 4; c++) acc[mb][nt][c] = 0.f;

            const uint32_t bbase = bB1 + (uint32_t)nq * (32 * 144);
            uint32_t bf[2][8];   // double buffer: 2 x (2 ldsm.x4)
            ldsm_x4(bf[0],     bbase);                    // ks=0, p=0
            ldsm_x4(bf[0] + 4, bbase + (16 * 144));       // ks=0, p=1
            #pragma unroll
            for (int ks = 0; ks < 4; ks++) {
                const int cur = ks & 1, nxt = cur ^ 1;
                if (ks < 3) {   // prefetch next k-step before consuming current
                    ldsm_x4(bf[nxt],     bbase + (uint32_t)(ks + 1) * 32);
                    ldsm_x4(bf[nxt] + 4, bbase + (16 * 144) + (uint32_t)(ks + 1) * 32);
                }
                #pragma unroll
                for (int p = 0; p < 2; p++) {
                    mma_f16(acc[0][2 * p],     a1[0][ks], bf[cur][4 * p],     bf[cur][4 * p + 1]);
                    mma_f16(acc[0][2 * p + 1], a1[0][ks], bf[cur][4 * p + 2], bf[cur][4 * p + 3]);
                    mma_f16(acc[1][2 * p],     a1[1][ks], bf[cur][4 * p],     bf[cur][4 * p + 1]);
                    mma_f16(acc[1][2 * p + 1], a1[1][ks], bf[cur][4 * p + 2], bf[cur][4 * p + 3]);
                }
            }
            // epilogue1: quarter -> af k-blocks 2nq, 2nq+1 (registers only)
            const uint32_t* tvb = tv2 + b * 64;
            #pragma unroll
            for (int j = 0; j < 2; j++) {
                int ksg = 2 * nq + j;
                uint32_t tv0 = tvb[(4 * nq + 2 * j) * 4 + qc];
                uint32_t tv1 = tvb[(4 * nq + 2 * j + 1) * 4 + qc];
                #pragma unroll
                for (int mb = 0; mb < 2; mb++) {
                    af[mb][ksg][0] = relu_add2(pack2(acc[mb][2 * j][0],     acc[mb][2 * j][1]),     tv0);
                    af[mb][ksg][1] = relu_add2(pack2(acc[mb][2 * j][2],     acc[mb][2 * j][3]),     tv0);
                    af[mb][ksg][2] = relu_add2(pack2(acc[mb][2 * j + 1][0], acc[mb][2 * j + 1][1]), tv1);
                    af[mb][ksg][3] = relu_add2(pack2(acc[mb][2 * j + 1][2], acc[mb][2 * j + 1][3]), tv1);
                }
            }
        }

        // ---- GEMM2 (M=32, K=128) in 4 n-quarters, B double-buffered ----
        float part[4] = {0.f, 0.f, 0.f, 0.f};
        #pragma unroll
        for (int nq = 0; nq < 4; nq++) {
            float acc2[2][4][4];
            #pragma unroll
            for (int mb = 0; mb < 2; mb++)
                #pragma unroll
                for (int nt = 0; nt < 4; nt++)
                    #pragma unroll
                    for (int c = 0; c < 4; c++) acc2[mb][nt][c] = 0.f;

            const uint32_t bbase = bB2 + (uint32_t)nq * (32 * 272);
            uint32_t bf[2][8];
            ldsm_x4(bf[0],     bbase);
            ldsm_x4(bf[0] + 4, bbase + (16 * 272));
            #pragma unroll
            for (int ks = 0; ks < 8; ks++) {
                const int cur = ks & 1, nxt = cur ^ 1;
                if (ks < 7) {
                    ldsm_x4(bf[nxt],     bbase + (uint32_t)(ks + 1) * 32);
                    ldsm_x4(bf[nxt] + 4, bbase + (16 * 272) + (uint32_t)(ks + 1) * 32);
                }
                #pragma unroll
                for (int p = 0; p < 2; p++) {
                    mma_f16(acc2[0][2 * p],     af[0][ks], bf[cur][4 * p],     bf[cur][4 * p + 1]);
                    mma_f16(acc2[0][2 * p + 1], af[0][ks], bf[cur][4 * p + 2], bf[cur][4 * p + 3]);
                    mma_f16(acc2[1][2 * p],     af[1][ks], bf[cur][4 * p],     bf[cur][4 * p + 1]);
                    mma_f16(acc2[1][2 * p + 1], af[1][ks], bf[cur][4 * p + 2], bf[cur][4 * p + 3]);
                }
            }
            const float* b2b = b2s + nq * 32;
            const float* w3b = w3s + nq * 32;
            #pragma unroll
            for (int nt = 0; nt < 4; nt++) {
                int h0 = nt * 8 + 2 * qc;
                float2 b2v = *(const float2*)(b2b + h0);
                float2 w3v = *(const float2*)(w3b + h0);
                #pragma unroll
                for (int mb = 0; mb < 2; mb++) {
                    part[mb * 2]     += fmaxf(acc2[mb][nt][0] + b2v.x, 0.f) * w3v.x
                                      + fmaxf(acc2[mb][nt][1] + b2v.y, 0.f) * w3v.y;
                    part[mb * 2 + 1] += fmaxf(acc2[mb][nt][2] + b2v.x, 0.f) * w3v.x
                                      + fmaxf(acc2[mb][nt][3] + b2v.y, 0.f) * w3v.y;
                }
            }
        }

        #pragma unroll
        for (int p = 0; p < 4; p++) {
            part[p] += __shfl_xor_sync(0xffffffff, part[p], 1);
            part[p] += __shfl_xor_sync(0xffffffff, part[p], 2);
        }
        if (qc == 0 && i < NN) {
            size_t obase = ((size_t)(b * NN + i)) * NN + jt * 128 + m32;
            out[obase + qr]      = part[0] + b3v;
            out[obase + 8 + qr]  = part[1] + b3v;
            out[obase + 16 + qr] = part[2] + b3v;
            out[obase + 24 + qr] = part[3] + b3v;
        }
    }
}

extern "C" void kernel_launch(void* const* d_in, const int* in_sizes, int n_in,
                              void* d_out, int out_size)
{
    const float* x  = (const float*)d_in[0];
    const float* y  = (const float*)d_in[1];
    const float* t  = (const float*)d_in[2];
    const float* W1 = (const float*)d_in[3];
    const float* b1 = (const float*)d_in[4];
    const float* W2 = (const float*)d_in[5];
    const float* b2 = (const float*)d_in[6];
    const float* W3 = (const float*)d_in[7];
    const float* b3 = (const float*)d_in[8];
    float* out = (float*)d_out;

    cudaFuncSetAttribute(pairmlp_f16,
                         cudaFuncAttributeMaxDynamicSharedMemorySize, SMEM_BYTES);
    pairmlp_f16<<<GRID, TPB, SMEM_BYTES>>>(x, y, t, W1, b1, W2, b2, W3, b3, out);
}

// round 13
// speedup vs baseline: 1.1481x; 1.0478x over previous
#include <cuda_runtime.h>
#include <cuda_fp16.h>
#include <cstdint>

#define NN 512
#define GRID 148
#define TPB 384
#define NT 2736   // 16 bjt x 171 i-triples

// ---- SMEM byte offsets ----
#define OB_W1T 0        // fp16 [n=128][k=64]  stride 72 fp16 (144B)  -> 18432
#define OB_W2T 18432    // fp16 [n=128][h=128] stride 136 fp16 (272B) -> 34816
#define OB_DH  53248    // fp16 diff [j=128][72] stride 144B, x3 groups -> 55296
#define OB_YS  108544   // f32 [128][68] -> 34816
#define OB_TV2 143360   // half2 tv [4][64] u32 -> 1024
#define OB_B2S 144384   // f32 [128]
#define OB_W3S 144896   // f32 [128]
#define SMEM_BYTES 145408

__device__ __forceinline__ uint32_t smem_u32(const void* p) {
    uint32_t a;
    asm("{ .reg .u64 t; cvta.to.shared.u64 t, %1; cvt.u32.u64 %0, t; }" : "=r"(a) : "l"(p));
    return a;
}
__device__ __forceinline__ uint32_t pack2(float e0, float e1) {
    __half2 h = __floats2half2_rn(e0, e1);
    return *(uint32_t*)&h;
}
__device__ __forceinline__ uint32_t relu_add2(uint32_t v, uint32_t tv) {
    __half2 a = __hadd2(*(__half2*)&v, *(__half2*)&tv);
    __half2 z = __float2half2_rn(0.f);
    __half2 m = __hmax2(a, z);
    return *(uint32_t*)&m;
}
__device__ __forceinline__ void ldsm_x4(uint32_t* r, uint32_t addr) {
    asm volatile("ldmatrix.sync.aligned.m8n8.x4.shared.b16 {%0,%1,%2,%3}, [%4];"
                 : "=r"(r[0]), "=r"(r[1]), "=r"(r[2]), "=r"(r[3]) : "r"(addr));
}
__device__ __forceinline__ void mma_f16(float* c, const uint32_t* a,
                                        uint32_t b0, uint32_t b1) {
    asm volatile("mma.sync.aligned.m16n8k16.row.col.f32.f16.f16.f32 "
                 "{%0,%1,%2,%3},{%4,%5,%6,%7},{%8,%9},{%0,%1,%2,%3};"
                 : "+f"(c[0]), "+f"(c[1]), "+f"(c[2]), "+f"(c[3])
                 : "r"(a[0]), "r"(a[1]), "r"(a[2]), "r"(a[3]), "r"(b0), "r"(b1));
}

__global__ void __launch_bounds__(TPB, 1)
pairmlp_f16(const float* __restrict__ x, const float* __restrict__ y,
            const float* __restrict__ t, const float* __restrict__ W1,
            const float* __restrict__ b1, const float* __restrict__ W2,
            const float* __restrict__ b2, const float* __restrict__ W3,
            const float* __restrict__ b3, float* __restrict__ out)
{
    extern __shared__ char sm[];
    float* ys  = (float*)(sm + OB_YS);
    uint32_t* tv2 = (uint32_t*)(sm + OB_TV2);
    float* b2s = (float*)(sm + OB_B2S);
    float* w3s = (float*)(sm + OB_W3S);
    __half* w1t = (__half*)(sm + OB_W1T);
    __half* w2t = (__half*)(sm + OB_W2T);

    const int tid = threadIdx.x;
    const int wid = tid >> 5;
    const int l   = tid & 31;
    const int grp = wid >> 2;          // 0..2: which i of the triple
    const int m32 = (wid & 3) * 32;    // warp's 32 j-rows
    const uint32_t sb = smem_u32(sm);
    const uint32_t dhb = sb + OB_DH + (uint32_t)grp * 18432u;

    // ---- one-time staging ----
    for (int idx = tid; idx < 64 * 128; idx += TPB) {
        int k = idx >> 7, n = idx & 127;
        w1t[n * 72 + k] = __float2half(W1[k * 128 + n]);
    }
    for (int idx = tid; idx < 128 * 128; idx += TPB) {
        int h = idx >> 7, n = idx & 127;
        w2t[n * 136 + h] = __float2half(W2[h * 128 + n]);
    }
    for (int idx = tid; idx < 4 * 64; idx += TPB) {
        int bb = idx >> 6, hp = idx & 63;
        float s0 = b1[2 * hp], s1 = b1[2 * hp + 1];
        #pragma unroll
        for (int d = 0; d < 32; d++) {
            float tv = t[bb * 32 + d];
            s0 += tv * W1[(64 + d) * 128 + 2 * hp];
            s1 += tv * W1[(64 + d) * 128 + 2 * hp + 1];
        }
        tv2[bb * 64 + hp] = pack2(s0, s1);
    }
    if (tid < 128) { b2s[tid] = b2[tid]; w3s[tid] = W3[tid]; }
    const float b3v = b3[0];
    __syncthreads();

    // ---- per-lane ldmatrix addresses ----
    const int g2 = l >> 3, r = l & 7;
    const uint32_t aA  = dhb + (uint32_t)(m32 + (g2 & 1) * 8 + r) * 144 + (uint32_t)(g2 >> 1) * 16;
    const uint32_t bB1 = sb + OB_W1T + (uint32_t)((g2 >> 1) * 8 + r) * 144 + (uint32_t)(g2 & 1) * 16;
    const uint32_t bB2 = sb + OB_W2T + (uint32_t)((g2 >> 1) * 8 + r) * 272 + (uint32_t)(g2 & 1) * 16;

    const int qr = l >> 2, qc = l & 3;
    const int start = (NT * blockIdx.x) / GRID;
    const int end   = (NT * (blockIdx.x + 1)) / GRID;
    int cur_bjt = -1;
    bool need_diff = true;

    // diff^2 -> this warp's DH strip for global row i_t (clamped), batch b_t
    auto do_diff = [&](int b_t, int ild_t) {
        const float4* xg = (const float4*)(x + ((size_t)(b_t * NN + ild_t)) * 64 + qc * 16);
        float4 xv[4];
        #pragma unroll
        for (int qq = 0; qq < 4; qq++) xv[qq] = xg[qq];
        #pragma unroll
        for (int rr = 0; rr < 4; rr++) {
            int row = m32 + qr + rr * 8;
            const float4* yrow = (const float4*)(ys + row * 68 + qc * 16);
            uint32_t base = dhb - sb + (uint32_t)row * 144 + (uint32_t)qc * 32;
            #pragma unroll
            for (int qq = 0; qq < 2; qq++) {
                float4 yv0 = yrow[2 * qq];
                float4 yv1 = yrow[2 * qq + 1];
                float d0 = xv[2 * qq].x - yv0.x, d1 = xv[2 * qq].y - yv0.y;
                float d2 = xv[2 * qq].z - yv0.z, d3 = xv[2 * qq].w - yv0.w;
                float e0 = xv[2 * qq + 1].x - yv1.x, e1 = xv[2 * qq + 1].y - yv1.y;
                float e2 = xv[2 * qq + 1].z - yv1.z, e3 = xv[2 * qq + 1].w - yv1.w;
                uint4 u;
                u.x = pack2(d0 * d0, d1 * d1);
                u.y = pack2(d2 * d2, d3 * d3);
                u.z = pack2(e0 * e0, e1 * e1);
                u.w = pack2(e2 * e2, e3 * e3);
                *(uint4*)(sm + base + qq * 16) = u;
            }
        }
    };

    for (int tau = start; tau < end; ++tau) {
        const int bjt = tau / 171;
        const int q   = tau - bjt * 171;
        const int b   = bjt >> 2;
        const int jt  = bjt & 3;
        const int i   = q * 3 + grp;
        const int ild = (i < NN) ? i : (NN - 1);

        if (bjt != cur_bjt) {
            __syncthreads();
            const float4* yg = (const float4*)(y + ((size_t)(b * NN + jt * 128)) * 64);
            for (int idx = tid; idx < 128 * 16; idx += TPB) {
                int rr = idx >> 4, gg = idx & 15;
                float4 v = yg[rr * 16 + gg];
                float* dst = ys + rr * 68 + gg * 4;
                dst[0] = v.x; dst[1] = v.y; dst[2] = v.z; dst[3] = v.w;
            }
            cur_bjt = bjt;
            __syncthreads();
            need_diff = true;
        }
        if (need_diff) do_diff(b, ild);   // fallback: first iter / bjt change
        __syncwarp();

        // ---- GEMM1 A fragments (diff), 2 m-blocks x 4 k-steps ----
        uint32_t a1[2][4][4];
        #pragma unroll
        for (int mb = 0; mb < 2; mb++)
            #pragma unroll
            for (int ks = 0; ks < 4; ks++)
                ldsm_x4(a1[mb][ks], aA + (uint32_t)mb * (16 * 144) + (uint32_t)ks * 32);

        // ---- GEMM1 (M=32, K=64) in 4 n-quarters; epilogue1 -> af in regs ----
        uint32_t af[2][8][4];
        #pragma unroll
        for (int nq = 0; nq < 4; nq++) {
            float acc[2][4][4];
            #pragma unroll
            for (int mb = 0; mb < 2; mb++)
                #pragma unroll
                for (int nt = 0; nt < 4; nt++)
                    #pragma unroll
                    for (int c = 0; c < 4; c++) acc[mb][nt][c] = 0.f;

            const uint32_t bbase = bB1 + (uint32_t)nq * (32 * 144);
            #pragma unroll
            for (int ks = 0; ks < 4; ks++) {
                #pragma unroll
                for (int p = 0; p < 2; p++) {
                    uint32_t bf[4];
                    ldsm_x4(bf, bbase + (uint32_t)p * (16 * 144) + (uint32_t)ks * 32);
                    mma_f16(acc[0][2 * p],     a1[0][ks], bf[0], bf[1]);
                    mma_f16(acc[0][2 * p + 1], a1[0][ks], bf[2], bf[3]);
                    mma_f16(acc[1][2 * p],     a1[1][ks], bf[0], bf[1]);
                    mma_f16(acc[1][2 * p + 1], a1[1][ks], bf[2], bf[3]);
                }
            }
            const uint32_t* tvb = tv2 + b * 64;
            #pragma unroll
            for (int j = 0; j < 2; j++) {
                int ksg = 2 * nq + j;
                uint32_t tv0 = tvb[(4 * nq + 2 * j) * 4 + qc];
                uint32_t tv1 = tvb[(4 * nq + 2 * j + 1) * 4 + qc];
                #pragma unroll
                for (int mb = 0; mb < 2; mb++) {
                    af[mb][ksg][0] = relu_add2(pack2(acc[mb][2 * j][0],     acc[mb][2 * j][1]),     tv0);
                    af[mb][ksg][1] = relu_add2(pack2(acc[mb][2 * j][2],     acc[mb][2 * j][3]),     tv0);
                    af[mb][ksg][2] = relu_add2(pack2(acc[mb][2 * j + 1][0], acc[mb][2 * j + 1][1]), tv1);
                    af[mb][ksg][3] = relu_add2(pack2(acc[mb][2 * j + 1][2], acc[mb][2 * j + 1][3]), tv1);
                }
            }
        }

        // pipeline decision: does tau+1 stay in this y-tile?
        const int tau1 = tau + 1;
        const bool pre = (tau1 < end) && (tau1 / 171 == bjt);

        // ---- GEMM2 (M=32, K=128) in 4 n-quarters; fused epilogue2 ----
        // diff(tau+1) interleaved after quarter 1 (DH strip is dead: a1 in regs)
        float part[4] = {0.f, 0.f, 0.f, 0.f};
        #pragma unroll
        for (int nq = 0; nq < 4; nq++) {
            float acc2[2][4][4];
            #pragma unroll
            for (int mb = 0; mb < 2; mb++)
                #pragma unroll
                for (int nt = 0; nt < 4; nt++)
                    #pragma unroll
                    for (int c = 0; c < 4; c++) acc2[mb][nt][c] = 0.f;

            const uint32_t bbase = bB2 + (uint32_t)nq * (32 * 272);
            #pragma unroll
            for (int ks = 0; ks < 8; ks++) {
                #pragma unroll
                for (int p = 0; p < 2; p++) {
                    uint32_t bf[4];
                    ldsm_x4(bf, bbase + (uint32_t)p * (16 * 272) + (uint32_t)ks * 32);
                    mma_f16(acc2[0][2 * p],     af[0][ks], bf[0], bf[1]);
                    mma_f16(acc2[0][2 * p + 1], af[0][ks], bf[2], bf[3]);
                    mma_f16(acc2[1][2 * p],     af[1][ks], bf[0], bf[1]);
                    mma_f16(acc2[1][2 * p + 1], af[1][ks], bf[2], bf[3]);
                }
            }
            const float* b2b = b2s + nq * 32;
            const float* w3b = w3s + nq * 32;
            #pragma unroll
            for (int nt = 0; nt < 4; nt++) {
                int h0 = nt * 8 + 2 * qc;
                float2 b2v = *(const float2*)(b2b + h0);
                float2 w3v = *(const float2*)(w3b + h0);
                #pragma unroll
                for (int mb = 0; mb < 2; mb++) {
                    part[mb * 2]     += fmaxf(acc2[mb][nt][0] + b2v.x, 0.f) * w3v.x
                                      + fmaxf(acc2[mb][nt][1] + b2v.y, 0.f) * w3v.y;
                    part[mb * 2 + 1] += fmaxf(acc2[mb][nt][2] + b2v.x, 0.f) * w3v.x
                                      + fmaxf(acc2[mb][nt][3] + b2v.y, 0.f) * w3v.y;
                }
            }

            if (nq == 1 && pre) {   // hide diff(tau+1) under remaining quarters
                const int qn = tau1 - bjt * 171;
                const int in_ = qn * 3 + grp;
                do_diff(b, (in_ < NN) ? in_ : (NN - 1));
            }
        }

        #pragma unroll
        for (int p = 0; p < 4; p++) {
            part[p] += __shfl_xor_sync(0xffffffff, part[p], 1);
            part[p] += __shfl_xor_sync(0xffffffff, part[p], 2);
        }
        if (qc == 0 && i < NN) {
            size_t obase = ((size_t)(b * NN + i)) * NN + jt * 128 + m32;
            out[obase + qr]      = part[0] + b3v;
            out[obase + 8 + qr]  = part[1] + b3v;
            out[obase + 16 + qr] = part[2] + b3v;
            out[obase + 24 + qr] = part[3] + b3v;
        }
        need_diff = !pre;
    }
}

extern "C" void kernel_launch(void* const* d_in, const int* in_sizes, int n_in,
                              void* d_out, int out_size)
{
    const float* x  = (const float*)d_in[0];
    const float* y  = (const float*)d_in[1];
    const float* t  = (const float*)d_in[2];
    const float* W1 = (const float*)d_in[3];
    const float* b1 = (const float*)d_in[4];
    const float* W2 = (const float*)d_in[5];
    const float* b2 = (const float*)d_in[6];
    const float* W3 = (const float*)d_in[7];
    const float* b3 = (const float*)d_in[8];
    float* out = (float*)d_out;

    cudaFuncSetAttribute(pairmlp_f16,
                         cudaFuncAttributeMaxDynamicSharedMemorySize, SMEM_BYTES);
    pairmlp_f16<<<GRID, TPB, SMEM_BYTES>>>(x, y, t, W1, b1, W2, b2, W3, b3, out);
}